// round 14
// baseline (speedup 1.0000x reference)
#include <cuda_runtime.h>
#include <cuda_fp16.h>
#include <cstdint>
#include <math.h>

// ---------------------------------------------------------------------------
// Problem dims
#define BB   4096
#define DD   1024
#define RB   2048
#define GN   (3*RB)     // 6144
#define MAXD 2560

// ---------------------------------------------------------------------------
// Device-global scratch (fp16 2-way splits only — no fp32 intermediates left)
__device__ __half g_X0[(size_t)BB*DD],  g_X1[(size_t)BB*DD];
__device__ __half g_P0[(size_t)BB*RB],  g_P1[(size_t)BB*RB];
__device__ __half g_Wi0[(size_t)RB*DD], g_Wi1[(size_t)RB*DD];
__device__ __half g_Wr0[(size_t)RB*RB], g_Wr1[(size_t)RB*RB];
__device__ __half g_Wg0[(size_t)GN*DD], g_Wg1[(size_t)GN*DD];

// ---------------------------------------------------------------------------
// Tiling: CTA 128x64 output tile, 512 threads (16 warps, warp tile 32x16),
// BK=64, 2-stage double buffer -> 96KB smem.
#define BK           64
#define A_TILE_BYTES (128 * 128)            // 128 rows x 64 fp16 = 16384 B
#define B_TILE_BYTES (64 * 128)             // 64 rows x 64 fp16  = 8192 B
#define STAGE_BYTES  (2*A_TILE_BYTES + 2*B_TILE_BYTES)   // 49152 B
#define B_OFF        (2*A_TILE_BYTES)
#define SMEM_SIZE    (2 * STAGE_BYTES)      // 98304 B
#define NTHREADS     512

__device__ __forceinline__ uint32_t smem_to_u32(const void* p) {
    uint32_t a;
    asm("{ .reg .u64 t; cvta.to.shared.u64 t, %1; cvt.u32.u64 %0, t; }" : "=r"(a) : "l"(p));
    return a;
}

__device__ __forceinline__ void ldsm_x4(uint32_t (&r)[4], uint32_t addr) {
    asm volatile("ldmatrix.sync.aligned.m8n8.x4.shared.b16 {%0,%1,%2,%3}, [%4];"
                 : "=r"(r[0]), "=r"(r[1]), "=r"(r[2]), "=r"(r[3]) : "r"(addr));
}

__device__ __forceinline__ void mma_f16(float (&c)[4], const uint32_t (&a)[4],
                                        const uint32_t* b) {
    asm volatile("mma.sync.aligned.m16n8k16.row.col.f32.f16.f16.f32 "
                 "{%0,%1,%2,%3}, {%4,%5,%6,%7}, {%8,%9}, {%0,%1,%2,%3};"
                 : "+f"(c[0]), "+f"(c[1]), "+f"(c[2]), "+f"(c[3])
                 : "r"(a[0]), "r"(a[1]), "r"(a[2]), "r"(a[3]), "r"(b[0]), "r"(b[1]));
}

// cp.async a (ROWS x 64) fp16 tile into SW128 smem (128B rows). 512 threads.
template<int ROWS>
__device__ __forceinline__ void cp_tile(uint32_t sm_tile, const __half* __restrict__ g,
                                        int ld, int tid) {
    constexpr int CHUNKS = ROWS * 8;       // 16B chunks
    #pragma unroll
    for (int i = 0; i < CHUNKS / NTHREADS; ++i) {
        int c   = tid + i * NTHREADS;
        int row = c >> 3;
        int ch  = c & 7;
        uint32_t off = (uint32_t)((row << 7) | (((ch ^ (row & 7))) << 4));
        const void* gp = g + (size_t)row * ld + (ch << 3);
        asm volatile("cp.async.cg.shared.global [%0], [%1], 16;"
                     :: "r"(sm_tile + off), "l"(gp));
    }
}
#define CP_COMMIT()  asm volatile("cp.async.commit_group;" ::: "memory")
#define CP_WAIT(n)   asm volatile("cp.async.wait_group %0;" :: "n"(n) : "memory")

// ---------------------------------------------------------------------------
// Load 2 ldmatrix.x4 A fragments (32 rows) for one split tile at k16-step ks.
__device__ __forceinline__ void load_afr(uint32_t sTile, int lane, int wm, int ks,
                                         uint32_t (&afr)[2][4]) {
    int r  = wm + (((lane >> 3) & 1) << 3) + (lane & 7);
    int kc = (ks << 1) + (lane >> 4);
    #pragma unroll
    for (int mi = 0; mi < 2; ++mi) {
        int rr = r + mi * 16;
        uint32_t addr = (uint32_t)((rr << 7) | (((kc ^ (rr & 7))) << 4));
        ldsm_x4(afr[mi], sTile + addr);
    }
}

// 4 MMAs of one product into one accumulator set (warp tile 32x16).
__device__ __forceinline__ void do_product(float (&acc)[2][2][4],
                                           const uint32_t (&afr)[2][4],
                                           const uint32_t (&bfr)[4]) {
    #pragma unroll
    for (int mi = 0; mi < 2; ++mi)
        #pragma unroll
        for (int nj = 0; nj < 2; ++nj)
            mma_f16(acc[mi][nj], afr[mi], &bfr[nj << 1]);
}

// ---------------------------------------------------------------------------
// One BK=64 window: 3 split-products, magnitude-ordered accumulation.
//   accL <- a0*b0 ; accS <- a0*b1, a1*b0 (a1*b1 ~2^-22 dropped)
__device__ __forceinline__ void compute_stage(uint32_t st, int lane, int wm, int wn,
                                              float (&accL)[2][2][4],
                                              float (&accS)[2][2][4])
{
    uint32_t sA = st;
    uint32_t sB = st + B_OFF;
    #pragma unroll
    for (int ks = 0; ks < 4; ++ks) {
        uint32_t bfr[2][4];
        {
            int r  = wn + (((lane >> 4) & 1) << 3) + (lane & 7);
            int kc = (ks << 1) + ((lane >> 3) & 1);
            uint32_t addr = (uint32_t)((r << 7) | (((kc ^ (r & 7))) << 4));
            ldsm_x4(bfr[0], sB + addr);
            ldsm_x4(bfr[1], sB + B_TILE_BYTES + addr);
        }
        {
            uint32_t afr[2][4];
            load_afr(sA + 0 * A_TILE_BYTES, lane, wm, ks, afr);
            do_product(accL, afr, bfr[0]);
            do_product(accS, afr, bfr[1]);
        }
        {
            uint32_t afr[2][4];
            load_afr(sA + 1 * A_TILE_BYTES, lane, wm, ks, afr);
            do_product(accS, afr, bfr[0]);
        }
    }
}

// ---------------------------------------------------------------------------
// One K-phase, 2-stage double buffer.
__device__ __forceinline__ void run_phase(
    const __half* __restrict__ A0, const __half* __restrict__ A1, int lda,
    const __half* __restrict__ B0, const __half* __restrict__ B1, int ldb,
    int nwin, uint32_t sb, int tid, int lane, int wm, int wn,
    float (&accL)[2][2][4], float (&accS)[2][2][4])
{
    __syncthreads();   // guard previous phase's smem reads

    cp_tile<128>(sb + 0 * A_TILE_BYTES, A0, lda, tid);
    cp_tile<128>(sb + 1 * A_TILE_BYTES, A1, lda, tid);
    cp_tile< 64>(sb + B_OFF + 0 * B_TILE_BYTES, B0, ldb, tid);
    cp_tile< 64>(sb + B_OFF + 1 * B_TILE_BYTES, B1, ldb, tid);
    CP_COMMIT();
    if (nwin > 1) {
        uint32_t st = sb + STAGE_BYTES;
        cp_tile<128>(st + 0 * A_TILE_BYTES, A0 + BK, lda, tid);
        cp_tile<128>(st + 1 * A_TILE_BYTES, A1 + BK, lda, tid);
        cp_tile< 64>(st + B_OFF + 0 * B_TILE_BYTES, B0 + BK, ldb, tid);
        cp_tile< 64>(st + B_OFF + 1 * B_TILE_BYTES, B1 + BK, ldb, tid);
        CP_COMMIT();
    }

    for (int w = 0; w < nwin; ++w) {
        if (w + 1 < nwin) { CP_WAIT(1); } else { CP_WAIT(0); }
        __syncthreads();
        compute_stage(sb + (w & 1) * STAGE_BYTES, lane, wm, wn, accL, accS);
        __syncthreads();
        if (w + 2 < nwin) {
            uint32_t st = sb + (w & 1) * STAGE_BYTES;   // stage just freed
            size_t koff = (size_t)(w + 2) * BK;
            cp_tile<128>(st + 0 * A_TILE_BYTES, A0 + koff, lda, tid);
            cp_tile<128>(st + 1 * A_TILE_BYTES, A1 + koff, lda, tid);
            cp_tile< 64>(st + B_OFF + 0 * B_TILE_BYTES, B0 + koff, ldb, tid);
            cp_tile< 64>(st + B_OFF + 1 * B_TILE_BYTES, B1 + koff, ldb, tid);
            CP_COMMIT();
        }
    }
}

#define ZERO_ACC(a) do { \
    _Pragma("unroll") for (int _i = 0; _i < 2; ++_i) \
    _Pragma("unroll") for (int _j = 0; _j < 2; ++_j) \
    _Pragma("unroll") for (int _l = 0; _l < 4; ++_l) (a)[_i][_j][_l] = 0.0f; \
} while (0)

// ---------------------------------------------------------------------------
// Fully fused kernel: each CTA produces the FINAL 128x64 state tile.
// Phases: Z = X*Wi^T + P*Wr^T ; i ; f ; o gates, combining in registers.
__global__ __launch_bounds__(NTHREADS, 1) void fused_kernel(
    const float* __restrict__ Praw, float* __restrict__ out)
{
    extern __shared__ char smem[];
    uint32_t sb = smem_to_u32(smem);
    int tid  = threadIdx.x;
    int lane = tid & 31;
    int wid  = tid >> 5;
    int wm   = (wid >> 2) * 32;    // warp M offset within 128 (4 m-warps)
    int wn   = (wid & 3) * 16;     // warp N offset within 64  (4 n-warps)

    int bz = blockIdx.x;           // 32 m-blocks x 32 n-blocks = 1024
    int bm = (bz >> 5) * 128;
    int bn = (bz & 31) * 64;

    float accL[2][2][4], accS[2][2][4];
    float inter[2][2][4];          // z -> t -> s0 (reused in place)

    // ---- Phase Z: X*Wi^T (K=1024) + P*Wr^T (K=2048) ----
    ZERO_ACC(accL); ZERO_ACC(accS);
    run_phase(g_X0 + (size_t)bm * DD, g_X1 + (size_t)bm * DD, DD,
              g_Wi0 + (size_t)bn * DD, g_Wi1 + (size_t)bn * DD, DD,
              DD / BK, sb, tid, lane, wm, wn, accL, accS);
    run_phase(g_P0 + (size_t)bm * RB, g_P1 + (size_t)bm * RB, RB,
              g_Wr0 + (size_t)bn * RB, g_Wr1 + (size_t)bn * RB, RB,
              RB / BK, sb, tid, lane, wm, wn, accL, accS);
    #pragma unroll
    for (int mi = 0; mi < 2; ++mi)
        #pragma unroll
        for (int nj = 0; nj < 2; ++nj)
            #pragma unroll
            for (int l = 0; l < 4; ++l)
                inter[mi][nj][l] = accL[mi][nj][l] + accS[mi][nj][l];   // z

    // ---- Phase i-gate: t = tanh(sigmoid(i) * z) ----
    ZERO_ACC(accL); ZERO_ACC(accS);
    run_phase(g_X0 + (size_t)bm * DD, g_X1 + (size_t)bm * DD, DD,
              g_Wg0 + (size_t)bn * DD, g_Wg1 + (size_t)bn * DD, DD,
              DD / BK, sb, tid, lane, wm, wn, accL, accS);
    #pragma unroll
    for (int mi = 0; mi < 2; ++mi)
        #pragma unroll
        for (int nj = 0; nj < 2; ++nj)
            #pragma unroll
            for (int l = 0; l < 4; ++l) {
                float g = accL[mi][nj][l] + accS[mi][nj][l];
                float ig = 1.0f / (1.0f + expf(-g));
                inter[mi][nj][l] = tanhf(ig * inter[mi][nj][l]);        // t
            }

    // ---- Phase f-gate: s0 = 0.9*sigmoid(f)*p + 0.1*t ----
    ZERO_ACC(accL); ZERO_ACC(accS);
    run_phase(g_X0 + (size_t)bm * DD, g_X1 + (size_t)bm * DD, DD,
              g_Wg0 + (size_t)(RB + bn) * DD, g_Wg1 + (size_t)(RB + bn) * DD, DD,
              DD / BK, sb, tid, lane, wm, wn, accL, accS);
    {
        int rbase = bm + wm + (lane >> 2);
        int cbase = bn + wn + ((lane & 3) << 1);
        #pragma unroll
        for (int mi = 0; mi < 2; ++mi)
            #pragma unroll
            for (int nj = 0; nj < 2; ++nj) {
                int r0 = rbase + mi * 16;
                int c0 = cbase + nj * 8;
                float2 pA = *reinterpret_cast<const float2*>(Praw + (size_t)r0 * MAXD + c0);
                float2 pB = *reinterpret_cast<const float2*>(Praw + (size_t)(r0 + 8) * MAXD + c0);
                float pv[4] = {pA.x, pA.y, pB.x, pB.y};
                #pragma unroll
                for (int l = 0; l < 4; ++l) {
                    float g = accL[mi][nj][l] + accS[mi][nj][l];
                    float fg = 1.0f / (1.0f + expf(-g));
                    inter[mi][nj][l] = 0.9f * (fg * pv[l]) + 0.1f * inter[mi][nj][l];  // s0
                }
            }
    }

    // ---- Phase o-gate: s = sigmoid(o)*s0, spike, store ----
    ZERO_ACC(accL); ZERO_ACC(accS);
    run_phase(g_X0 + (size_t)bm * DD, g_X1 + (size_t)bm * DD, DD,
              g_Wg0 + (size_t)(2 * RB + bn) * DD, g_Wg1 + (size_t)(2 * RB + bn) * DD, DD,
              DD / BK, sb, tid, lane, wm, wn, accL, accS);
    {
        int rbase = bm + wm + (lane >> 2);
        int cbase = bn + wn + ((lane & 3) << 1);
        #pragma unroll
        for (int mi = 0; mi < 2; ++mi)
            #pragma unroll
            for (int nj = 0; nj < 2; ++nj) {
                int r0 = rbase + mi * 16;
                int c0 = cbase + nj * 8;
                float v[4];
                #pragma unroll
                for (int l = 0; l < 4; ++l) {
                    float g = accL[mi][nj][l] + accS[mi][nj][l];
                    float og = 1.0f / (1.0f + expf(-g));
                    float s = og * inter[mi][nj][l];
                    if (s > 0.5f) s -= 0.5f;
                    v[l] = s;
                }
                *reinterpret_cast<float2*>(out + (size_t)r0 * MAXD + c0)       = make_float2(v[0], v[1]);
                *reinterpret_cast<float2*>(out + (size_t)(r0 + 8) * MAXD + c0) = make_float2(v[2], v[3]);
            }
    }
}

// ---------------------------------------------------------------------------
// Fused fp32 -> 2x fp16 split kernel (one launch for all 5 tensors).
#define S_X   ((size_t)BB*DD/4)
#define S_P   ((size_t)BB*RB/4)
#define S_WI  ((size_t)RB*DD/4)
#define S_WR  ((size_t)RB*RB/4)
#define S_WG  ((size_t)GN*DD/4)
#define S_TOT (S_X + S_P + S_WI + S_WR + S_WG)

__device__ __forceinline__ void split_store(const float4 v, __half* d0, __half* d1, size_t o)
{
    float a[4] = {v.x, v.y, v.z, v.w};
    __half h0[4], h1[4];
    #pragma unroll
    for (int i = 0; i < 4; ++i) {
        h0[i] = __float2half_rn(a[i]);
        float r = a[i] - __half2float(h0[i]);
        h1[i] = __float2half_rn(r);
    }
    *reinterpret_cast<uint2*>(d0 + o) = *reinterpret_cast<uint2*>(h0);
    *reinterpret_cast<uint2*>(d1 + o) = *reinterpret_cast<uint2*>(h1);
}

__global__ void split_all_kernel(const float* __restrict__ X, const float* __restrict__ P,
                                 const float* __restrict__ Wi, const float* __restrict__ Wr,
                                 const float* __restrict__ Wg)
{
    size_t i4 = (size_t)blockIdx.x * blockDim.x + threadIdx.x;
    if (i4 >= S_TOT) return;

    const float* src; __half *d0, *d1; size_t e; int cols, srcld;
    if (i4 < S_X) {
        src = X;  d0 = g_X0;  d1 = g_X1;  e = i4 * 4;            cols = DD; srcld = DD;
    } else if (i4 < S_X + S_P) {
        src = P;  d0 = g_P0;  d1 = g_P1;  e = (i4 - S_X) * 4;    cols = RB; srcld = MAXD;
    } else if (i4 < S_X + S_P + S_WI) {
        src = Wi; d0 = g_Wi0; d1 = g_Wi1; e = (i4 - S_X - S_P) * 4; cols = DD; srcld = DD;
    } else if (i4 < S_X + S_P + S_WI + S_WR) {
        src = Wr; d0 = g_Wr0; d1 = g_Wr1; e = (i4 - S_X - S_P - S_WI) * 4; cols = RB; srcld = RB;
    } else {
        src = Wg; d0 = g_Wg0; d1 = g_Wg1; e = (i4 - S_X - S_P - S_WI - S_WR) * 4; cols = DD; srcld = DD;
    }
    int row = (int)(e / cols);
    int col = (int)(e % cols);
    float4 v = *reinterpret_cast<const float4*>(src + (size_t)row * srcld + col);
    split_store(v, d0, d1, e);
}

// ---------------------------------------------------------------------------
// Zero the pad region out[:, 2048:2560].
__global__ void pad_kernel(float* __restrict__ out)
{
    size_t idx = (size_t)blockIdx.x * blockDim.x + threadIdx.x;   // float4 units
    size_t tot = (size_t)BB * (MAXD - RB) / 4;                    // 524288
    if (idx >= tot) return;
    int perrow = (MAXD - RB) / 4;                                  // 128
    int row = (int)(idx / perrow);
    int c4  = (int)(idx % perrow);
    *reinterpret_cast<float4*>(out + (size_t)row * MAXD + RB + c4 * 4) =
        make_float4(0.0f, 0.0f, 0.0f, 0.0f);
}

// ---------------------------------------------------------------------------
extern "C" void kernel_launch(void* const* d_in, const int* in_sizes, int n_in,
                              void* d_out, int out_size)
{
    const float* X    = (const float*)d_in[0];
    const float* P    = (const float*)d_in[1];
    const float* Win  = (const float*)d_in[2];
    const float* Wres = (const float*)d_in[3];
    const float* Wg   = (const float*)d_in[4];
    float* out = (float*)d_out;

    static bool attr_set = false;
    if (!attr_set) {
        cudaFuncSetAttribute(fused_kernel,
                             cudaFuncAttributeMaxDynamicSharedMemorySize, SMEM_SIZE);
        attr_set = true;
    }

    split_all_kernel<<<(int)((S_TOT + 255) / 256), 256>>>(X, P, Win, Wres, Wg);
    pad_kernel<<<(int)(((size_t)BB * (MAXD - RB) / 4 + 255) / 256), 256>>>(out);
    fused_kernel<<<1024, NTHREADS, SMEM_SIZE>>>(P, out);
}

// round 15
// speedup vs baseline: 1.2587x; 1.2587x over previous
#include <cuda_runtime.h>
#include <cuda_fp16.h>
#include <cstdint>
#include <math.h>

// ---------------------------------------------------------------------------
// Problem dims
#define BB   4096
#define DD   1024
#define RB   2048
#define GN   (3*RB)     // 6144
#define MAXD 2560

// ---------------------------------------------------------------------------
// Device-global scratch
__device__ __half g_X0[(size_t)BB*DD],  g_X1[(size_t)BB*DD];
__device__ __half g_P0[(size_t)BB*RB],  g_P1[(size_t)BB*RB];
__device__ __half g_Wi0[(size_t)RB*DD], g_Wi1[(size_t)RB*DD];
__device__ __half g_Wr0[(size_t)RB*RB], g_Wr1[(size_t)RB*RB];
__device__ __half g_Wg0[(size_t)GN*DD], g_Wg1[(size_t)GN*DD];
__device__ float g_G[(size_t)BB*GN];    // sigmoid(gates)

// ---------------------------------------------------------------------------
// Tiling: CTA 128x64, 256 threads (8 warps, warp tile 32x32), BK=64,
// 2-stage double buffer -> 96KB smem -> 2 CTAs/SM.  (R13 proven config.)
#define BK           64
#define A_TILE_BYTES (128 * 128)
#define B_TILE_BYTES (64 * 128)
#define STAGE_BYTES  (2*A_TILE_BYTES + 2*B_TILE_BYTES)   // 49152 B
#define B_OFF        (2*A_TILE_BYTES)
#define SMEM_SIZE    (2 * STAGE_BYTES)                    // 98304 B

__device__ __forceinline__ uint32_t smem_to_u32(const void* p) {
    uint32_t a;
    asm("{ .reg .u64 t; cvta.to.shared.u64 t, %1; cvt.u32.u64 %0, t; }" : "=r"(a) : "l"(p));
    return a;
}

__device__ __forceinline__ void ldsm_x4(uint32_t (&r)[4], uint32_t addr) {
    asm volatile("ldmatrix.sync.aligned.m8n8.x4.shared.b16 {%0,%1,%2,%3}, [%4];"
                 : "=r"(r[0]), "=r"(r[1]), "=r"(r[2]), "=r"(r[3]) : "r"(addr));
}

__device__ __forceinline__ void mma_f16(float (&c)[4], const uint32_t (&a)[4],
                                        const uint32_t* b) {
    asm volatile("mma.sync.aligned.m16n8k16.row.col.f32.f16.f16.f32 "
                 "{%0,%1,%2,%3}, {%4,%5,%6,%7}, {%8,%9}, {%0,%1,%2,%3};"
                 : "+f"(c[0]), "+f"(c[1]), "+f"(c[2]), "+f"(c[3])
                 : "r"(a[0]), "r"(a[1]), "r"(a[2]), "r"(a[3]), "r"(b[0]), "r"(b[1]));
}

// cp.async a (ROWS x 64) fp16 tile into SW128 smem (128B rows). 256 threads.
template<int ROWS>
__device__ __forceinline__ void cp_tile(uint32_t sm_tile, const __half* __restrict__ g,
                                        int ld, int tid) {
    constexpr int CHUNKS = ROWS * 8;
    #pragma unroll
    for (int i = 0; i < CHUNKS / 256; ++i) {
        int c   = tid + (i << 8);
        int row = c >> 3;
        int ch  = c & 7;
        uint32_t off = (uint32_t)((row << 7) | (((ch ^ (row & 7))) << 4));
        const void* gp = g + (size_t)row * ld + (ch << 3);
        asm volatile("cp.async.cg.shared.global [%0], [%1], 16;"
                     :: "r"(sm_tile + off), "l"(gp));
    }
}
#define CP_COMMIT()  asm volatile("cp.async.commit_group;" ::: "memory")
#define CP_WAIT(n)   asm volatile("cp.async.wait_group %0;" :: "n"(n) : "memory")

// ---------------------------------------------------------------------------
__device__ __forceinline__ void load_afr(uint32_t sTile, int lane, int wm, int ks,
                                         uint32_t (&afr)[2][4]) {
    int r  = wm + (((lane >> 3) & 1) << 3) + (lane & 7);
    int kc = (ks << 1) + (lane >> 4);
    #pragma unroll
    for (int mi = 0; mi < 2; ++mi) {
        int rr = r + mi * 16;
        uint32_t addr = (uint32_t)((rr << 7) | (((kc ^ (rr & 7))) << 4));
        ldsm_x4(afr[mi], sTile + addr);
    }
}

// 8 MMAs of one product (warp tile 32x32).
__device__ __forceinline__ void do_product(float (&acc)[2][4][4],
                                           const uint32_t (&afr)[2][4],
                                           const uint32_t (&bfr)[2][4]) {
    #pragma unroll
    for (int mi = 0; mi < 2; ++mi)
        #pragma unroll
        for (int nj = 0; nj < 4; ++nj)
            mma_f16(acc[mi][nj], afr[mi], &bfr[nj >> 1][(nj & 1) << 1]);
}

// One BK=64 window: 3 split-products, magnitude-ordered accumulation.
__device__ __forceinline__ void compute_stage(uint32_t st, int lane, int wm, int wn,
                                              float (&accL)[2][4][4],
                                              float (&accS)[2][4][4])
{
    uint32_t sA = st;
    uint32_t sB = st + B_OFF;
    #pragma unroll
    for (int ks = 0; ks < 4; ++ks) {
        uint32_t bfr[2][2][4];
        {
            int r  = wn + (((lane >> 4) & 1) << 3) + (lane & 7);
            int kc = (ks << 1) + ((lane >> 3) & 1);
            #pragma unroll
            for (int nj2 = 0; nj2 < 2; ++nj2) {
                int rr = r + nj2 * 16;
                uint32_t addr = (uint32_t)((rr << 7) | (((kc ^ (rr & 7))) << 4));
                #pragma unroll
                for (int s = 0; s < 2; ++s)
                    ldsm_x4(bfr[s][nj2], sB + s * B_TILE_BYTES + addr);
            }
        }
        {
            uint32_t afr[2][4];
            load_afr(sA + 0 * A_TILE_BYTES, lane, wm, ks, afr);
            do_product(accL, afr, bfr[0]);
            do_product(accS, afr, bfr[1]);
        }
        {
            uint32_t afr[2][4];
            load_afr(sA + 1 * A_TILE_BYTES, lane, wm, ks, afr);
            do_product(accS, afr, bfr[0]);
        }
    }
}

// One K-phase, 2-stage double buffer.
__device__ __forceinline__ void run_phase(
    const __half* __restrict__ A0, const __half* __restrict__ A1, int lda,
    const __half* __restrict__ B0, const __half* __restrict__ B1, int ldb,
    int nwin, uint32_t sb, int tid, int lane, int wm, int wn,
    float (&accL)[2][4][4], float (&accS)[2][4][4])
{
    __syncthreads();

    cp_tile<128>(sb + 0 * A_TILE_BYTES, A0, lda, tid);
    cp_tile<128>(sb + 1 * A_TILE_BYTES, A1, lda, tid);
    cp_tile< 64>(sb + B_OFF + 0 * B_TILE_BYTES, B0, ldb, tid);
    cp_tile< 64>(sb + B_OFF + 1 * B_TILE_BYTES, B1, ldb, tid);
    CP_COMMIT();
    if (nwin > 1) {
        uint32_t st = sb + STAGE_BYTES;
        cp_tile<128>(st + 0 * A_TILE_BYTES, A0 + BK, lda, tid);
        cp_tile<128>(st + 1 * A_TILE_BYTES, A1 + BK, lda, tid);
        cp_tile< 64>(st + B_OFF + 0 * B_TILE_BYTES, B0 + BK, ldb, tid);
        cp_tile< 64>(st + B_OFF + 1 * B_TILE_BYTES, B1 + BK, ldb, tid);
        CP_COMMIT();
    }

    for (int w = 0; w < nwin; ++w) {
        if (w + 1 < nwin) { CP_WAIT(1); } else { CP_WAIT(0); }
        __syncthreads();
        compute_stage(sb + (w & 1) * STAGE_BYTES, lane, wm, wn, accL, accS);
        __syncthreads();
        if (w + 2 < nwin) {
            uint32_t st = sb + (w & 1) * STAGE_BYTES;
            size_t koff = (size_t)(w + 2) * BK;
            cp_tile<128>(st + 0 * A_TILE_BYTES, A0 + koff, lda, tid);
            cp_tile<128>(st + 1 * A_TILE_BYTES, A1 + koff, lda, tid);
            cp_tile< 64>(st + B_OFF + 0 * B_TILE_BYTES, B0 + koff, ldb, tid);
            cp_tile< 64>(st + B_OFF + 1 * B_TILE_BYTES, B1 + koff, ldb, tid);
            CP_COMMIT();
        }
    }
}

// ---------------------------------------------------------------------------
// Kernel 1: gates GEMM. Grid 3072: bm = (bz/96)*128, bn = (bz%96)*64.
// Writes sigmoid(X @ Wg^T) to g_G.
__global__ __launch_bounds__(256, 2) void gemm_gates_kernel()
{
    extern __shared__ char smem[];
    uint32_t sb = smem_to_u32(smem);
    int tid  = threadIdx.x;
    int lane = tid & 31;
    int wid  = tid >> 5;
    int wm   = (wid >> 1) * 32;
    int wn   = (wid & 1) * 32;

    int bz = blockIdx.x;
    int bm = (bz / 96) * 128;
    int bn = (bz % 96) * 64;

    float accL[2][4][4], accS[2][4][4];
    #pragma unroll
    for (int i = 0; i < 2; ++i)
        #pragma unroll
        for (int j = 0; j < 4; ++j)
            #pragma unroll
            for (int l = 0; l < 4; ++l) { accL[i][j][l] = 0.0f; accS[i][j][l] = 0.0f; }

    run_phase(g_X0 + (size_t)bm * DD, g_X1 + (size_t)bm * DD, DD,
              g_Wg0 + (size_t)bn * DD, g_Wg1 + (size_t)bn * DD, DD,
              DD / BK, sb, tid, lane, wm, wn, accL, accS);

    int rbase = bm + wm + (lane >> 2);
    int cbase = bn + wn + ((lane & 3) << 1);
    #pragma unroll
    for (int mi = 0; mi < 2; ++mi) {
        #pragma unroll
        for (int nj = 0; nj < 4; ++nj) {
            int r0 = rbase + mi * 16;
            int c0 = cbase + nj * 8;
            float v0 = 1.0f / (1.0f + expf(-(accL[mi][nj][0] + accS[mi][nj][0])));
            float v1 = 1.0f / (1.0f + expf(-(accL[mi][nj][1] + accS[mi][nj][1])));
            float v2 = 1.0f / (1.0f + expf(-(accL[mi][nj][2] + accS[mi][nj][2])));
            float v3 = 1.0f / (1.0f + expf(-(accL[mi][nj][3] + accS[mi][nj][3])));
            *reinterpret_cast<float2*>(g_G + (size_t)r0 * GN + c0)       = make_float2(v0, v1);
            *reinterpret_cast<float2*>(g_G + (size_t)(r0 + 8) * GN + c0) = make_float2(v2, v3);
        }
    }
}

// ---------------------------------------------------------------------------
// Kernel 2: Z GEMM (X*Wi^T + P*Wr^T) with fused state epilogue.
// Grid 1024: bm = (bz>>5)*128, bn = (bz&31)*64. Reads g_G + P, writes out.
__global__ __launch_bounds__(256, 2) void gemm_z_combine_kernel(
    const float* __restrict__ Praw, float* __restrict__ out)
{
    extern __shared__ char smem[];
    uint32_t sb = smem_to_u32(smem);
    int tid  = threadIdx.x;
    int lane = tid & 31;
    int wid  = tid >> 5;
    int wm   = (wid >> 1) * 32;
    int wn   = (wid & 1) * 32;

    int bz = blockIdx.x;
    int bm = (bz >> 5) * 128;
    int bn = (bz & 31) * 64;

    float accL[2][4][4], accS[2][4][4];
    #pragma unroll
    for (int i = 0; i < 2; ++i)
        #pragma unroll
        for (int j = 0; j < 4; ++j)
            #pragma unroll
            for (int l = 0; l < 4; ++l) { accL[i][j][l] = 0.0f; accS[i][j][l] = 0.0f; }

    run_phase(g_X0 + (size_t)bm * DD, g_X1 + (size_t)bm * DD, DD,
              g_Wi0 + (size_t)bn * DD, g_Wi1 + (size_t)bn * DD, DD,
              DD / BK, sb, tid, lane, wm, wn, accL, accS);
    run_phase(g_P0 + (size_t)bm * RB, g_P1 + (size_t)bm * RB, RB,
              g_Wr0 + (size_t)bn * RB, g_Wr1 + (size_t)bn * RB, RB,
              RB / BK, sb, tid, lane, wm, wn, accL, accS);

    // Epilogue: state = o * (0.9*f*p + 0.1*tanh(i*z)); spike; store.
    int rbase = bm + wm + (lane >> 2);
    int cbase = bn + wn + ((lane & 3) << 1);
    #pragma unroll
    for (int mi = 0; mi < 2; ++mi) {
        #pragma unroll
        for (int nj = 0; nj < 4; ++nj) {
            int r0 = rbase + mi * 16;
            int c0 = cbase + nj * 8;
            #pragma unroll
            for (int half = 0; half < 2; ++half) {
                int r = r0 + half * 8;
                float z0 = accL[mi][nj][half*2+0] + accS[mi][nj][half*2+0];
                float z1 = accL[mi][nj][half*2+1] + accS[mi][nj][half*2+1];
                const float* grow = g_G + (size_t)r * GN;
                float2 gi = *reinterpret_cast<const float2*>(grow + c0);
                float2 gf = *reinterpret_cast<const float2*>(grow + RB + c0);
                float2 go = *reinterpret_cast<const float2*>(grow + 2 * RB + c0);
                float2 p  = *reinterpret_cast<const float2*>(Praw + (size_t)r * MAXD + c0);
                float s0 = 0.9f * (gf.x * p.x) + 0.1f * tanhf(gi.x * z0);
                float s1 = 0.9f * (gf.y * p.y) + 0.1f * tanhf(gi.y * z1);
                s0 = go.x * s0;
                s1 = go.y * s1;
                if (s0 > 0.5f) s0 -= 0.5f;
                if (s1 > 0.5f) s1 -= 0.5f;
                *reinterpret_cast<float2*>(out + (size_t)r * MAXD + c0) = make_float2(s0, s1);
            }
        }
    }
}

// ---------------------------------------------------------------------------
// Fused fp32 -> 2x fp16 split kernel.
#define S_X   ((size_t)BB*DD/4)
#define S_P   ((size_t)BB*RB/4)
#define S_WI  ((size_t)RB*DD/4)
#define S_WR  ((size_t)RB*RB/4)
#define S_WG  ((size_t)GN*DD/4)
#define S_TOT (S_X + S_P + S_WI + S_WR + S_WG)

__device__ __forceinline__ void split_store(const float4 v, __half* d0, __half* d1, size_t o)
{
    float a[4] = {v.x, v.y, v.z, v.w};
    __half h0[4], h1[4];
    #pragma unroll
    for (int i = 0; i < 4; ++i) {
        h0[i] = __float2half_rn(a[i]);
        float r = a[i] - __half2float(h0[i]);
        h1[i] = __float2half_rn(r);
    }
    *reinterpret_cast<uint2*>(d0 + o) = *reinterpret_cast<uint2*>(h0);
    *reinterpret_cast<uint2*>(d1 + o) = *reinterpret_cast<uint2*>(h1);
}

__global__ void split_all_kernel(const float* __restrict__ X, const float* __restrict__ P,
                                 const float* __restrict__ Wi, const float* __restrict__ Wr,
                                 const float* __restrict__ Wg)
{
    size_t i4 = (size_t)blockIdx.x * blockDim.x + threadIdx.x;
    if (i4 >= S_TOT) return;

    const float* src; __half *d0, *d1; size_t e; int cols, srcld;
    if (i4 < S_X) {
        src = X;  d0 = g_X0;  d1 = g_X1;  e = i4 * 4;            cols = DD; srcld = DD;
    } else if (i4 < S_X + S_P) {
        src = P;  d0 = g_P0;  d1 = g_P1;  e = (i4 - S_X) * 4;    cols = RB; srcld = MAXD;
    } else if (i4 < S_X + S_P + S_WI) {
        src = Wi; d0 = g_Wi0; d1 = g_Wi1; e = (i4 - S_X - S_P) * 4; cols = DD; srcld = DD;
    } else if (i4 < S_X + S_P + S_WI + S_WR) {
        src = Wr; d0 = g_Wr0; d1 = g_Wr1; e = (i4 - S_X - S_P - S_WI) * 4; cols = RB; srcld = RB;
    } else {
        src = Wg; d0 = g_Wg0; d1 = g_Wg1; e = (i4 - S_X - S_P - S_WI - S_WR) * 4; cols = DD; srcld = DD;
    }
    int row = (int)(e / cols);
    int col = (int)(e % cols);
    float4 v = *reinterpret_cast<const float4*>(src + (size_t)row * srcld + col);
    split_store(v, d0, d1, e);
}

// ---------------------------------------------------------------------------
// Zero the pad region out[:, 2048:2560].
__global__ void pad_kernel(float* __restrict__ out)
{
    size_t idx = (size_t)blockIdx.x * blockDim.x + threadIdx.x;
    size_t tot = (size_t)BB * (MAXD - RB) / 4;
    if (idx >= tot) return;
    int perrow = (MAXD - RB) / 4;
    int row = (int)(idx / perrow);
    int c4  = (int)(idx % perrow);
    *reinterpret_cast<float4*>(out + (size_t)row * MAXD + RB + c4 * 4) =
        make_float4(0.0f, 0.0f, 0.0f, 0.0f);
}

// ---------------------------------------------------------------------------
extern "C" void kernel_launch(void* const* d_in, const int* in_sizes, int n_in,
                              void* d_out, int out_size)
{
    const float* X    = (const float*)d_in[0];
    const float* P    = (const float*)d_in[1];
    const float* Win  = (const float*)d_in[2];
    const float* Wres = (const float*)d_in[3];
    const float* Wg   = (const float*)d_in[4];
    float* out = (float*)d_out;

    static bool attr_set = false;
    if (!attr_set) {
        cudaFuncSetAttribute(gemm_gates_kernel,
                             cudaFuncAttributeMaxDynamicSharedMemorySize, SMEM_SIZE);
        cudaFuncSetAttribute(gemm_z_combine_kernel,
                             cudaFuncAttributeMaxDynamicSharedMemorySize, SMEM_SIZE);
        attr_set = true;
    }

    split_all_kernel<<<(int)((S_TOT + 255) / 256), 256>>>(X, P, Win, Wres, Wg);
    pad_kernel<<<(int)(((size_t)BB * (MAXD - RB) / 4 + 255) / 256), 256>>>(out);
    gemm_gates_kernel<<<3072, 256, SMEM_SIZE>>>();
    gemm_z_combine_kernel<<<1024, 256, SMEM_SIZE>>>(P, out);
}

// round 16
// speedup vs baseline: 1.2629x; 1.0033x over previous
#include <cuda_runtime.h>
#include <cuda_fp16.h>
#include <cstdint>
#include <math.h>

// ---------------------------------------------------------------------------
// Problem dims
#define BB   4096
#define DD   1024
#define RB   2048
#define GN   (3*RB)     // 6144
#define MAXD 2560

// ---------------------------------------------------------------------------
// Device-global scratch
__device__ __half g_X0[(size_t)BB*DD],  g_X1[(size_t)BB*DD];
__device__ __half g_P0[(size_t)BB*RB],  g_P1[(size_t)BB*RB];
__device__ __half g_Wi0[(size_t)RB*DD], g_Wi1[(size_t)RB*DD];
__device__ __half g_Wr0[(size_t)RB*RB], g_Wr1[(size_t)RB*RB];
__device__ __half g_Wg0[(size_t)GN*DD], g_Wg1[(size_t)GN*DD];
__device__ float g_G[(size_t)BB*GN];    // sigmoid(gates)

// ---------------------------------------------------------------------------
// Tiling: CTA 128x64, 256 threads (8 warps, warp tile 32x32), BK=64,
// 2-stage double buffer -> 96KB smem -> 2 CTAs/SM.  (Proven config.)
#define BK           64
#define A_TILE_BYTES (128 * 128)
#define B_TILE_BYTES (64 * 128)
#define STAGE_BYTES  (2*A_TILE_BYTES + 2*B_TILE_BYTES)   // 49152 B
#define B_OFF        (2*A_TILE_BYTES)
#define SMEM_SIZE    (2 * STAGE_BYTES)                    // 98304 B

__device__ __forceinline__ uint32_t smem_to_u32(const void* p) {
    uint32_t a;
    asm("{ .reg .u64 t; cvta.to.shared.u64 t, %1; cvt.u32.u64 %0, t; }" : "=r"(a) : "l"(p));
    return a;
}

__device__ __forceinline__ void ldsm_x4(uint32_t (&r)[4], uint32_t addr) {
    asm volatile("ldmatrix.sync.aligned.m8n8.x4.shared.b16 {%0,%1,%2,%3}, [%4];"
                 : "=r"(r[0]), "=r"(r[1]), "=r"(r[2]), "=r"(r[3]) : "r"(addr));
}

__device__ __forceinline__ void mma_f16(float (&c)[4], const uint32_t (&a)[4],
                                        const uint32_t* b) {
    asm volatile("mma.sync.aligned.m16n8k16.row.col.f32.f16.f16.f32 "
                 "{%0,%1,%2,%3}, {%4,%5,%6,%7}, {%8,%9}, {%0,%1,%2,%3};"
                 : "+f"(c[0]), "+f"(c[1]), "+f"(c[2]), "+f"(c[3])
                 : "r"(a[0]), "r"(a[1]), "r"(a[2]), "r"(a[3]), "r"(b[0]), "r"(b[1]));
}

// cp.async a (ROWS x 64) fp16 tile into SW128 smem (128B rows). 256 threads.
template<int ROWS>
__device__ __forceinline__ void cp_tile(uint32_t sm_tile, const __half* __restrict__ g,
                                        int ld, int tid) {
    constexpr int CHUNKS = ROWS * 8;
    #pragma unroll
    for (int i = 0; i < CHUNKS / 256; ++i) {
        int c   = tid + (i << 8);
        int row = c >> 3;
        int ch  = c & 7;
        uint32_t off = (uint32_t)((row << 7) | (((ch ^ (row & 7))) << 4));
        const void* gp = g + (size_t)row * ld + (ch << 3);
        asm volatile("cp.async.cg.shared.global [%0], [%1], 16;"
                     :: "r"(sm_tile + off), "l"(gp));
    }
}
#define CP_COMMIT()  asm volatile("cp.async.commit_group;" ::: "memory")
#define CP_WAIT(n)   asm volatile("cp.async.wait_group %0;" :: "n"(n) : "memory")

// ---------------------------------------------------------------------------
__device__ __forceinline__ void load_afr(uint32_t sTile, int lane, int wm, int ks,
                                         uint32_t (&afr)[2][4]) {
    int r  = wm + (((lane >> 3) & 1) << 3) + (lane & 7);
    int kc = (ks << 1) + (lane >> 4);
    #pragma unroll
    for (int mi = 0; mi < 2; ++mi) {
        int rr = r + mi * 16;
        uint32_t addr = (uint32_t)((rr << 7) | (((kc ^ (rr & 7))) << 4));
        ldsm_x4(afr[mi], sTile + addr);
    }
}

// 8 MMAs of one product (warp tile 32x32).
__device__ __forceinline__ void do_product(float (&acc)[2][4][4],
                                           const uint32_t (&afr)[2][4],
                                           const uint32_t (&bfr)[2][4]) {
    #pragma unroll
    for (int mi = 0; mi < 2; ++mi)
        #pragma unroll
        for (int nj = 0; nj < 4; ++nj)
            mma_f16(acc[mi][nj], afr[mi], &bfr[nj >> 1][(nj & 1) << 1]);
}

// One BK=64 window: 3 split-products, magnitude-ordered accumulation.
//   accL <- a0*b0 ; accS <- a0*b1, a1*b0 (a1*b1 ~2^-22 dropped)
__device__ __forceinline__ void compute_stage(uint32_t st, int lane, int wm, int wn,
                                              float (&accL)[2][4][4],
                                              float (&accS)[2][4][4])
{
    uint32_t sA = st;
    uint32_t sB = st + B_OFF;
    #pragma unroll
    for (int ks = 0; ks < 4; ++ks) {
        uint32_t bfr[2][2][4];
        {
            int r  = wn + (((lane >> 4) & 1) << 3) + (lane & 7);
            int kc = (ks << 1) + ((lane >> 3) & 1);
            #pragma unroll
            for (int nj2 = 0; nj2 < 2; ++nj2) {
                int rr = r + nj2 * 16;
                uint32_t addr = (uint32_t)((rr << 7) | (((kc ^ (rr & 7))) << 4));
                #pragma unroll
                for (int s = 0; s < 2; ++s)
                    ldsm_x4(bfr[s][nj2], sB + s * B_TILE_BYTES + addr);
            }
        }
        {
            uint32_t afr[2][4];
            load_afr(sA + 0 * A_TILE_BYTES, lane, wm, ks, afr);
            do_product(accL, afr, bfr[0]);
            do_product(accS, afr, bfr[1]);
        }
        {
            uint32_t afr[2][4];
            load_afr(sA + 1 * A_TILE_BYTES, lane, wm, ks, afr);
            do_product(accS, afr, bfr[0]);
        }
    }
}

// ---------------------------------------------------------------------------
// Window issue helpers (uniform branches; one cp.async group per window).
__device__ __forceinline__ void issue_win_z(int w, uint32_t sb, int bm, int bn, int tid)
{
    uint32_t st = sb + (w & 1) * STAGE_BYTES;
    if (w < DD / BK) {                       // phase 1: X * Wi^T
        size_t koff = (size_t)w * BK;
        cp_tile<128>(st + 0 * A_TILE_BYTES, g_X0 + (size_t)bm * DD + koff, DD, tid);
        cp_tile<128>(st + 1 * A_TILE_BYTES, g_X1 + (size_t)bm * DD + koff, DD, tid);
        cp_tile< 64>(st + B_OFF + 0 * B_TILE_BYTES, g_Wi0 + (size_t)bn * DD + koff, DD, tid);
        cp_tile< 64>(st + B_OFF + 1 * B_TILE_BYTES, g_Wi1 + (size_t)bn * DD + koff, DD, tid);
    } else {                                 // phase 2: P * Wr^T
        size_t koff = (size_t)(w - DD / BK) * BK;
        cp_tile<128>(st + 0 * A_TILE_BYTES, g_P0 + (size_t)bm * RB + koff, RB, tid);
        cp_tile<128>(st + 1 * A_TILE_BYTES, g_P1 + (size_t)bm * RB + koff, RB, tid);
        cp_tile< 64>(st + B_OFF + 0 * B_TILE_BYTES, g_Wr0 + (size_t)bn * RB + koff, RB, tid);
        cp_tile< 64>(st + B_OFF + 1 * B_TILE_BYTES, g_Wr1 + (size_t)bn * RB + koff, RB, tid);
    }
    CP_COMMIT();
}

__device__ __forceinline__ void issue_win_g(int w, uint32_t sb, int bm, int bn, int tid)
{
    uint32_t st = sb + (w & 1) * STAGE_BYTES;
    size_t koff = (size_t)w * BK;
    cp_tile<128>(st + 0 * A_TILE_BYTES, g_X0 + (size_t)bm * DD + koff, DD, tid);
    cp_tile<128>(st + 1 * A_TILE_BYTES, g_X1 + (size_t)bm * DD + koff, DD, tid);
    cp_tile< 64>(st + B_OFF + 0 * B_TILE_BYTES, g_Wg0 + (size_t)bn * DD + koff, DD, tid);
    cp_tile< 64>(st + B_OFF + 1 * B_TILE_BYTES, g_Wg1 + (size_t)bn * DD + koff, DD, tid);
    CP_COMMIT();
}

#define ZERO_ACC2(aL, aS) do { \
    _Pragma("unroll") for (int _i = 0; _i < 2; ++_i) \
    _Pragma("unroll") for (int _j = 0; _j < 4; ++_j) \
    _Pragma("unroll") for (int _l = 0; _l < 4; ++_l) { (aL)[_i][_j][_l] = 0.0f; (aS)[_i][_j][_l] = 0.0f; } \
} while (0)

// ---------------------------------------------------------------------------
// Kernel 1: gates GEMM. Grid 3072: bm=(bz/96)*128, bn=(bz%96)*64.
// Single-barrier-per-window pipeline. Writes sigmoid(X @ Wg^T) to g_G.
__global__ __launch_bounds__(256, 2) void gemm_gates_kernel()
{
    extern __shared__ char smem[];
    uint32_t sb = smem_to_u32(smem);
    int tid  = threadIdx.x;
    int lane = tid & 31;
    int wid  = tid >> 5;
    int wm   = (wid >> 1) * 32;
    int wn   = (wid & 1) * 32;

    int bz = blockIdx.x;
    int bm = (bz / 96) * 128;
    int bn = (bz % 96) * 64;

    float accL[2][4][4], accS[2][4][4];
    ZERO_ACC2(accL, accS);

    const int NW = DD / BK;                 // 16
    issue_win_g(0, sb, bm, bn, tid);
    for (int w = 0; w < NW; ++w) {
        CP_WAIT(0);                          // group w landed
        __syncthreads();                     // all threads done compute(w-1)
        if (w + 1 < NW) issue_win_g(w + 1, sb, bm, bn, tid);
        compute_stage(sb + (w & 1) * STAGE_BYTES, lane, wm, wn, accL, accS);
    }

    int rbase = bm + wm + (lane >> 2);
    int cbase = bn + wn + ((lane & 3) << 1);
    #pragma unroll
    for (int mi = 0; mi < 2; ++mi) {
        #pragma unroll
        for (int nj = 0; nj < 4; ++nj) {
            int r0 = rbase + mi * 16;
            int c0 = cbase + nj * 8;
            float v0 = 1.0f / (1.0f + expf(-(accL[mi][nj][0] + accS[mi][nj][0])));
            float v1 = 1.0f / (1.0f + expf(-(accL[mi][nj][1] + accS[mi][nj][1])));
            float v2 = 1.0f / (1.0f + expf(-(accL[mi][nj][2] + accS[mi][nj][2])));
            float v3 = 1.0f / (1.0f + expf(-(accL[mi][nj][3] + accS[mi][nj][3])));
            *reinterpret_cast<float2*>(g_G + (size_t)r0 * GN + c0)       = make_float2(v0, v1);
            *reinterpret_cast<float2*>(g_G + (size_t)(r0 + 8) * GN + c0) = make_float2(v2, v3);
        }
    }
}

// ---------------------------------------------------------------------------
// Kernel 2: Z GEMM (X*Wi^T then P*Wr^T as ONE continuous 48-window stream)
// with fused state epilogue. Grid 1024: bm=(bz>>5)*128, bn=(bz&31)*64.
__global__ __launch_bounds__(256, 2) void gemm_z_combine_kernel(
    const float* __restrict__ Praw, float* __restrict__ out)
{
    extern __shared__ char smem[];
    uint32_t sb = smem_to_u32(smem);
    int tid  = threadIdx.x;
    int lane = tid & 31;
    int wid  = tid >> 5;
    int wm   = (wid >> 1) * 32;
    int wn   = (wid & 1) * 32;

    int bz = blockIdx.x;
    int bm = (bz >> 5) * 128;
    int bn = (bz & 31) * 64;

    float accL[2][4][4], accS[2][4][4];
    ZERO_ACC2(accL, accS);

    const int NW = (DD + RB) / BK;          // 48
    issue_win_z(0, sb, bm, bn, tid);
    for (int w = 0; w < NW; ++w) {
        CP_WAIT(0);
        __syncthreads();
        if (w + 1 < NW) issue_win_z(w + 1, sb, bm, bn, tid);
        compute_stage(sb + (w & 1) * STAGE_BYTES, lane, wm, wn, accL, accS);
    }

    // Epilogue: state = o * (0.9*f*p + 0.1*tanh(i*z)); spike; store.
    int rbase = bm + wm + (lane >> 2);
    int cbase = bn + wn + ((lane & 3) << 1);
    #pragma unroll
    for (int mi = 0; mi < 2; ++mi) {
        #pragma unroll
        for (int nj = 0; nj < 4; ++nj) {
            int r0 = rbase + mi * 16;
            int c0 = cbase + nj * 8;
            #pragma unroll
            for (int half = 0; half < 2; ++half) {
                int r = r0 + half * 8;
                float z0 = accL[mi][nj][half*2+0] + accS[mi][nj][half*2+0];
                float z1 = accL[mi][nj][half*2+1] + accS[mi][nj][half*2+1];
                const float* grow = g_G + (size_t)r * GN;
                float2 gi = *reinterpret_cast<const float2*>(grow + c0);
                float2 gf = *reinterpret_cast<const float2*>(grow + RB + c0);
                float2 go = *reinterpret_cast<const float2*>(grow + 2 * RB + c0);
                float2 p  = *reinterpret_cast<const float2*>(Praw + (size_t)r * MAXD + c0);
                float s0 = 0.9f * (gf.x * p.x) + 0.1f * tanhf(gi.x * z0);
                float s1 = 0.9f * (gf.y * p.y) + 0.1f * tanhf(gi.y * z1);
                s0 = go.x * s0;
                s1 = go.y * s1;
                if (s0 > 0.5f) s0 -= 0.5f;
                if (s1 > 0.5f) s1 -= 0.5f;
                *reinterpret_cast<float2*>(out + (size_t)r * MAXD + c0) = make_float2(s0, s1);
            }
        }
    }
}

// ---------------------------------------------------------------------------
// Fused fp32 -> 2x fp16 split kernel + output pad zeroing in one launch.
#define S_X    ((size_t)BB*DD/4)
#define S_P    ((size_t)BB*RB/4)
#define S_WI   ((size_t)RB*DD/4)
#define S_WR   ((size_t)RB*RB/4)
#define S_WG   ((size_t)GN*DD/4)
#define S_TOT  (S_X + S_P + S_WI + S_WR + S_WG)
#define S_PAD  ((size_t)BB*(MAXD-RB)/4)
#define S_ALL  (S_TOT + S_PAD)

__device__ __forceinline__ void split_store(const float4 v, __half* d0, __half* d1, size_t o)
{
    float a[4] = {v.x, v.y, v.z, v.w};
    __half h0[4], h1[4];
    #pragma unroll
    for (int i = 0; i < 4; ++i) {
        h0[i] = __float2half_rn(a[i]);
        float r = a[i] - __half2float(h0[i]);
        h1[i] = __float2half_rn(r);
    }
    *reinterpret_cast<uint2*>(d0 + o) = *reinterpret_cast<uint2*>(h0);
    *reinterpret_cast<uint2*>(d1 + o) = *reinterpret_cast<uint2*>(h1);
}

__global__ void split_all_kernel(const float* __restrict__ X, const float* __restrict__ P,
                                 const float* __restrict__ Wi, const float* __restrict__ Wr,
                                 const float* __restrict__ Wg, float* __restrict__ out)
{
    size_t i4 = (size_t)blockIdx.x * blockDim.x + threadIdx.x;
    if (i4 >= S_ALL) return;

    if (i4 >= S_TOT) {                       // pad region: out[:, 2048:2560] = 0
        size_t idx = i4 - S_TOT;
        int perrow = (MAXD - RB) / 4;
        int row = (int)(idx / perrow);
        int c4  = (int)(idx % perrow);
        *reinterpret_cast<float4*>(out + (size_t)row * MAXD + RB + c4 * 4) =
            make_float4(0.0f, 0.0f, 0.0f, 0.0f);
        return;
    }

    const float* src; __half *d0, *d1; size_t e; int cols, srcld;
    if (i4 < S_X) {
        src = X;  d0 = g_X0;  d1 = g_X1;  e = i4 * 4;            cols = DD; srcld = DD;
    } else if (i4 < S_X + S_P) {
        src = P;  d0 = g_P0;  d1 = g_P1;  e = (i4 - S_X) * 4;    cols = RB; srcld = MAXD;
    } else if (i4 < S_X + S_P + S_WI) {
        src = Wi; d0 = g_Wi0; d1 = g_Wi1; e = (i4 - S_X - S_P) * 4; cols = DD; srcld = DD;
    } else if (i4 < S_X + S_P + S_WI + S_WR) {
        src = Wr; d0 = g_Wr0; d1 = g_Wr1; e = (i4 - S_X - S_P - S_WI) * 4; cols = RB; srcld = RB;
    } else {
        src = Wg; d0 = g_Wg0; d1 = g_Wg1; e = (i4 - S_X - S_P - S_WI - S_WR) * 4; cols = DD; srcld = DD;
    }
    int row = (int)(e / cols);
    int col = (int)(e % cols);
    float4 v = *reinterpret_cast<const float4*>(src + (size_t)row * srcld + col);
    split_store(v, d0, d1, e);
}

// ---------------------------------------------------------------------------
extern "C" void kernel_launch(void* const* d_in, const int* in_sizes, int n_in,
                              void* d_out, int out_size)
{
    const float* X    = (const float*)d_in[0];
    const float* P    = (const float*)d_in[1];
    const float* Win  = (const float*)d_in[2];
    const float* Wres = (const float*)d_in[3];
    const float* Wg   = (const float*)d_in[4];
    float* out = (float*)d_out;

    static bool attr_set = false;
    if (!attr_set) {
        cudaFuncSetAttribute(gemm_gates_kernel,
                             cudaFuncAttributeMaxDynamicSharedMemorySize, SMEM_SIZE);
        cudaFuncSetAttribute(gemm_z_combine_kernel,
                             cudaFuncAttributeMaxDynamicSharedMemorySize, SMEM_SIZE);
        attr_set = true;
    }

    split_all_kernel<<<(int)((S_ALL + 255) / 256), 256>>>(X, P, Win, Wres, Wg, out);
    gemm_gates_kernel<<<3072, 256, SMEM_SIZE>>>();
    gemm_z_combine_kernel<<<1024, 256, SMEM_SIZE>>>(P, out);
}